// round 14
// baseline (speedup 1.0000x reference)
#include <cuda_runtime.h>
#include <cuda_bf16.h>
#include <math.h>

#define BSZ    128
#define DIN    512
#define DMODEL 2048
#define MEMN   25
#define NSY    256
#define NSYNC  32896
#define OUTD   1000
#define OUTPAD 1024
#define NITER  24
#define N1     4096
#define SK1    7
#define SK2    28
#define NST    6
#define TILEN  64
#define STFLT  (TILEN * 16)         // 1024 floats per B stage
#define STBYT  (STFLT * 4)          // 4096
#define GSMEM  (NST * STBYT)        // 24576 bytes dynamic smem
#define NKS1   (DMODEL / 16)        // 128 stages
#define NKS2   (NSYNC / 16)         // 2056 stages
#define CERT_OFF (BSZ * OUTD * NITER)

// init ranges
#define R1 (DIN * BSZ)
#define R2 (MEMN * DMODEL * BSZ)
#define R3 (DMODEL * BSZ)
#define R4 (MEMN * 64 * DMODEL)
#define R5 (64 * DMODEL)
#define RTOT (R1 + R2 + R3 + R4 + R5)

typedef unsigned long long ULL;
typedef unsigned U32;

// ---------------- persistent scratch ----------------
__device__ float g_trace[MEMN * DMODEL * BSZ];
__device__ float g_actT [DMODEL * BSZ];
__device__ U32   g_actF [DMODEL * BSZ];     // tf32, MMA-fragment-native
__device__ U32   g_syncF[NSYNC * BSZ];
__device__ float g_xT   [DIN * BSZ];
__device__ float g_z0   [BSZ * N1];
__device__ float g_zp   [8 * BSZ * N1];
__device__ float g_alpha[NSYNC * BSZ];
__device__ float g_r    [NSYNC];
__device__ int   g_pi   [NSYNC];
__device__ int   g_pj   [NSYNC];
__device__ float g_part [36 * BSZ * OUTD];
__device__ float g_pred [BSZ * OUTD];
__device__ float g_w1i  [DMODEL * MEMN * 64];
__device__ float g_w2T  [DMODEL * 64];
// blocked+swizzled B: [n_tile64][k_stage][64][16]
__device__ float g_synB [(size_t)(N1 / TILEN) * NKS1 * STFLT];
__device__ float g_outB [(size_t)(OUTPAD / TILEN) * NKS2 * STFLT];

__device__ __forceinline__ float sigmoidf_(float x) { return 1.0f / (1.0f + expf(-x)); }
__device__ __forceinline__ ULL dup2(float x) {
    ULL r; unsigned u = __float_as_uint(x);
    asm("mov.b64 %0, {%1, %1};" : "=l"(r) : "r"(u)); return r;
}
__device__ __forceinline__ ULL pack2(float lo, float hi) {
    ULL r; asm("mov.b64 %0, {%1, %2};" : "=l"(r) : "r"(__float_as_uint(lo)), "r"(__float_as_uint(hi)));
    return r;
}
__device__ __forceinline__ void fma2(ULL& d, ULL a, ULL b) {
    asm("fma.rn.f32x2 %0, %1, %2, %3;" : "=l"(d) : "l"(a), "l"(b), "l"(d));
}
__device__ __forceinline__ float lo32(ULL v) { return __uint_as_float((unsigned)v); }
__device__ __forceinline__ float hi32(ULL v) { return __uint_as_float((unsigned)(v >> 32)); }

__device__ __forceinline__ U32 f2tf(float v) {
    U32 u; asm("cvt.rna.tf32.f32 %0, %1;" : "=r"(u) : "f"(v)); return u;
}

// Fragment-native tf32 A store (m16n8k8 A-frag; lane's 4 regs contiguous 16B)
__device__ __forceinline__ void tf_store(float v, int k, int m, U32* __restrict__ F) {
    int kb = k >> 3, kc = k & 7, mb = m >> 4, mr = m & 15;
    int lane = (mr & 7) * 4 + (kc & 3);
    int r = ((kc >> 2) << 1) | (mr >> 3);
    F[(kb * 8 + mb) * 128 + lane * 4 + r] = f2tf(v);
}

__device__ __forceinline__ U32 smem_u32(const void* p) {
    U32 a; asm("{ .reg .u64 t; cvta.to.shared.u64 t, %1; cvt.u32.u64 %0, t; }" : "=r"(a) : "l"(p));
    return a;
}
__device__ __forceinline__ void mbar_init(U32 mbar, U32 cnt) {
    asm volatile("mbarrier.init.shared.b64 [%0], %1;" :: "r"(mbar), "r"(cnt) : "memory");
}
__device__ __forceinline__ void mbar_expect_tx(U32 mbar, U32 bytes) {
    asm volatile("mbarrier.arrive.expect_tx.shared.b64 _, [%0], %1;" :: "r"(mbar), "r"(bytes) : "memory");
}
__device__ __forceinline__ void mbar_wait(U32 mbar, U32 parity) {
    asm volatile("{\n\t.reg .pred P;\n\tWL%=:\n\t"
                 "mbarrier.try_wait.parity.acquire.cta.shared::cta.b64 P, [%0], %1, 0x989680;\n\t"
                 "@P bra.uni WD%=;\n\tbra.uni WL%=;\n\tWD%=:\n\t}"
                 :: "r"(mbar), "r"(parity) : "memory");
}
__device__ __forceinline__ void bulk_ld(U32 sdst, const void* g, U32 bytes, U32 mbar) {
    asm volatile("cp.async.bulk.shared::cluster.global.mbarrier::complete_tx::bytes "
                 "[%0], [%1], %2, [%3];"
                 :: "r"(sdst), "l"(g), "r"(bytes), "r"(mbar) : "memory");
}

__device__ __forceinline__ void mma_tf32(float* c, const U32* a, U32 b0, U32 b1) {
    asm volatile("mma.sync.aligned.m16n8k8.row.col.f32.tf32.tf32.f32 "
                 "{%0,%1,%2,%3}, {%4,%5,%6,%7}, {%8,%9}, {%0,%1,%2,%3};"
                 : "+f"(c[0]), "+f"(c[1]), "+f"(c[2]), "+f"(c[3])
                 : "r"(a[0]), "r"(a[1]), "r"(a[2]), "r"(a[3]), "r"(b0), "r"(b1));
}

struct AFrag { uint4 f[2][2]; };

__device__ __forceinline__ void load_afrag(const U32* __restrict__ AF, int ks, int lane,
                                           int warp_m, AFrag& a) {
#pragma unroll
    for (int kb2 = 0; kb2 < 2; kb2++)
#pragma unroll
        for (int mb2 = 0; mb2 < 2; mb2++)
            a.f[kb2][mb2] = *(const uint4*)(AF +
                (((ks * 2 + kb2) * 8 + warp_m * 2 + mb2) * 128 + lane * 4));
}

// 16 MMAs per k16 stage; B from swizzled blocked stage [64][16]
__device__ __forceinline__ void mma_step(float acc[2][4][4], const AFrag& a,
                                         const U32* __restrict__ sB, int warp_n, int lane) {
#pragma unroll
    for (int kb2 = 0; kb2 < 2; kb2++) {
        U32 b[4][2];
#pragma unroll
        for (int j = 0; j < 4; j++) {
            int nn = warp_n * 32 + j * 8 + (lane >> 2);
            int sw = ((nn >> 1) & 3) << 2;
            int pos = (kb2 * 8 + (lane & 3)) ^ sw;
            b[j][0] = sB[nn * 16 + pos];
            b[j][1] = sB[nn * 16 + (pos ^ 4)];
        }
#pragma unroll
        for (int j = 0; j < 4; j++) {
            mma_tf32(acc[0][j], (const U32*)&a.f[kb2][0], b[j][0], b[j][1]);
            mma_tf32(acc[1][j], (const U32*)&a.f[kb2][1], b[j][0], b[j][1]);
        }
    }
}

// ======== TF32 GEMM: 64-wide tiles, bulk-copy B, mbarrier ring, 3 CTAs/SM ========
__global__ __launch_bounds__(256, 3) void k_gemm_mma(
    const U32* __restrict__ AF, const float* __restrict__ Bblk,
    int nksTot, int Nmax, int SK, float* __restrict__ C, int ldc)
{
    extern __shared__ U32 sB[];        // [NST][1024]
    __shared__ ULL mbars[NST];
    int tid = threadIdx.x;
    int lane = tid & 31, wid = tid >> 5;
    int warp_m = wid >> 1, warp_n = wid & 1;
    int n0 = blockIdx.x * TILEN;
    int z = blockIdx.y;
    int s0 = (int)((long long)z * nksTot / SK);
    int s1 = (int)((long long)(z + 1) * nksTot / SK);
    int nst = s1 - s0;
    const float* Btile = Bblk + (size_t)blockIdx.x * nksTot * STFLT;

    float acc[2][4][4];
#pragma unroll
    for (int i = 0; i < 2; i++)
#pragma unroll
        for (int j = 0; j < 4; j++)
#pragma unroll
            for (int q = 0; q < 4; q++) acc[i][j][q] = 0.0f;

    U32 mb0 = smem_u32(&mbars[0]);
    if (tid == 0) {
#pragma unroll
        for (int s = 0; s < NST; s++) mbar_init(mb0 + s * 8, 1);
    }
    __syncthreads();
    if (tid == 0) {
#pragma unroll
        for (int p = 0; p < 4; p++) {
            if (p < nst) {
                mbar_expect_tx(mb0 + p * 8, STBYT);
                bulk_ld(smem_u32(&sB[p * STFLT]), Btile + (size_t)(s0 + p) * STFLT,
                        STBYT, mb0 + p * 8);
            }
        }
    }
    AFrag a0, a1;
    load_afrag(AF, s0, lane, warp_m, a0);
    if (nst > 1) load_afrag(AF, s0 + 1, lane, warp_m, a1);

    for (int c = 0; c < nst; c += 2) {
        mbar_wait(mb0 + (c % NST) * 8, (U32)((c / NST) & 1));
        if (c + 1 < nst) mbar_wait(mb0 + ((c + 1) % NST) * 8, (U32)(((c + 1) / NST) & 1));
        __syncthreads();    // slot-reuse ordering
        if (tid == 0) {
#pragma unroll
            for (int u = 0; u < 2; u++) {
                int cc = c + 4 + u;
                if (cc < nst) {
                    int sl = cc % NST;
                    mbar_expect_tx(mb0 + sl * 8, STBYT);
                    bulk_ld(smem_u32(&sB[sl * STFLT]), Btile + (size_t)(s0 + cc) * STFLT,
                            STBYT, mb0 + sl * 8);
                }
            }
        }
        mma_step(acc, a0, &sB[(c % NST) * STFLT], warp_n, lane);
        if (c + 2 < nst) load_afrag(AF, s0 + c + 2, lane, warp_m, a0);
        if (c + 1 < nst) {
            mma_step(acc, a1, &sB[((c + 1) % NST) * STFLT], warp_n, lane);
            if (c + 3 < nst) load_afrag(AF, s0 + c + 3, lane, warp_m, a1);
        }
    }

    float* Cz = C + (size_t)z * BSZ * ldc;
#pragma unroll
    for (int i = 0; i < 2; i++) {
        int m0 = warp_m * 32 + i * 16 + (lane >> 2);
#pragma unroll
        for (int j = 0; j < 4; j++) {
            int n = n0 + warp_n * 32 + j * 8 + 2 * (lane & 3);
            if (n < Nmax) {
                Cz[(size_t)m0 * ldc + n]       = acc[i][j][0];
                Cz[(size_t)(m0 + 8) * ldc + n] = acc[i][j][2];
            }
            if (n + 1 < Nmax) {
                Cz[(size_t)m0 * ldc + n + 1]       = acc[i][j][1];
                Cz[(size_t)(m0 + 8) * ldc + n + 1] = acc[i][j][3];
            }
        }
    }
}

// ------- build blocked+swizzled tf32 B: [tile64][stage][64][16] from src[k][ncols] -------
__global__ __launch_bounds__(256) void k_transpose_blk(const float* __restrict__ src, int ncols,
                                                       int nksTot, float* __restrict__ dst)
{
    __shared__ float ts[16 * 68];
    int tile = blockIdx.x, ks = blockIdx.y;
    int tid = threadIdx.x;
#pragma unroll
    for (int i = 0; i < 4; i++) {
        int e = i * 256 + tid;          // e = kk*64 + n
        int kk = e >> 6, n = e & 63;
        int col = tile * TILEN + n;
        ts[kk * 68 + n] = (col < ncols) ? src[(size_t)(ks * 16 + kk) * ncols + col] : 0.0f;
    }
    __syncthreads();
    float* out = dst + ((size_t)tile * nksTot + ks) * STFLT;
#pragma unroll
    for (int i = 0; i < 4; i++) {
        int o = i * 256 + tid;          // o = r*16 + kpos
        int r = o >> 4, kpos = o & 15;
        int kk = kpos ^ (((r >> 1) & 3) << 2);
        out[o] = __uint_as_float(f2tf(ts[kk * 68 + r]));
    }
}

// ---------------- fused init ----------------
__global__ void k_init_all(const float* __restrict__ x, const float* __restrict__ strc,
                           const float* __restrict__ sas, const float* __restrict__ w1,
                           const float* __restrict__ w2) {
    long long idx = blockIdx.x * 256LL + threadIdx.x;
    if (idx < R1) {
        int i = (int)idx;
        g_xT[i] = x[(i & 127) * DIN + (i >> 7)];
        return;
    }
    idx -= R1;
    if (idx < R2) {
        int i = (int)idx;
        int d = (i >> 7) & (DMODEL - 1);
        int m = i >> 18;
        g_trace[i] = strc[d * MEMN + m];
        return;
    }
    idx -= R2;
    if (idx < R3) {
        int i = (int)idx;
        int d = i >> 7, b = i & 127;
        float v = sas[d];
        g_actT[i] = v;
        tf_store(v, d, b, g_actF);
        return;
    }
    idx -= R3;
    if (idx < R4) {
        int i = (int)idx;
        int d = i & (DMODEL - 1);
        int rem = i >> 11;
        int h = rem & 63, m = rem >> 6;
        g_w1i[((d * MEMN + m) * 32 + (h & 31)) * 2 + (h >> 5)] = w1[i];
        return;
    }
    idx -= R4;
    if (idx < R5) {
        int i = (int)idx;
        g_w2T[(i & (DMODEL - 1)) * 64 + (i >> 11)] = w2[i];
    }
}

__global__ void k_init_alpha(const float* __restrict__ sas, const float* __restrict__ decay,
                             const int* __restrict__ il, const int* __restrict__ ir) {
    int p = blockIdx.x, b = threadIdx.x;
    float pf = (float)p;
    int i = (int)floorf(256.5f - sqrtf(256.5f * 256.5f - 2.0f * pf));
    if (i < 0) i = 0;
    if (i > NSY - 1) i = NSY - 1;
    while (i > 0 && (i * NSY - i * (i - 1) / 2) > p) i--;
    while (i < NSY - 1 && ((i + 1) * NSY - (i + 1) * i / 2) <= p) i++;
    int j = i + (p - (i * NSY - i * (i - 1) / 2));
    if (b == 0) {
        g_pi[p] = i; g_pj[p] = j;
        g_r[p] = expf(-fminf(fmaxf(decay[p], 0.0f), 15.0f));
    }
    g_alpha[p * BSZ + b] = sas[il[i]] * sas[ir[j]];
}

// ---------------- FMA2 GEMM (one-time z0 = x @ W_top, exact fp32) ----------------
__global__ __launch_bounds__(256) void k_gemm_f2(
    const float* __restrict__ A, const float* __restrict__ B,
    int ldb, int nkb, float* __restrict__ C, int ldc)
{
    __shared__ float As[2][8][128];
    __shared__ float Bs[2][8][128];
    int n0 = blockIdx.x * 128;
    int tid = threadIdx.x;
    int lr = tid >> 5, lc = (tid & 31) * 4;
    int ty = tid >> 4, tx = tid & 15;
    ULL acc[8][4];
#pragma unroll
    for (int i = 0; i < 8; i++)
#pragma unroll
        for (int j = 0; j < 4; j++) acc[i][j] = 0ULL;
    float4 pa = *(const float4*)(A + lr * BSZ + lc);
    float4 pb = *(const float4*)(B + (size_t)lr * ldb + n0 + lc);
    *(float4*)&As[0][lr][lc] = pa;
    *(float4*)&Bs[0][lr][lc] = pb;
    __syncthreads();
    int buf = 0;
    for (int kb = 0; kb < nkb; kb++) {
        bool has = (kb + 1 < nkb);
        if (has) {
            int krow = (kb + 1) * 8 + lr;
            pa = *(const float4*)(A + krow * BSZ + lc);
            pb = *(const float4*)(B + (size_t)krow * ldb + n0 + lc);
        }
#pragma unroll
        for (int kk = 0; kk < 8; kk++) {
            float a[8];
            *(float4*)&a[0] = *(const float4*)&As[buf][kk][ty * 8];
            *(float4*)&a[4] = *(const float4*)&As[buf][kk][ty * 8 + 4];
            ULL bv[4];
            const ULL* bp = (const ULL*)&Bs[buf][kk][tx * 8];
#pragma unroll
            for (int j = 0; j < 4; j++) bv[j] = bp[j];
#pragma unroll
            for (int i = 0; i < 8; i++) {
                ULL ad = dup2(a[i]);
#pragma unroll
                for (int j = 0; j < 4; j++) fma2(acc[i][j], ad, bv[j]);
            }
        }
        if (has) {
            *(float4*)&As[buf ^ 1][lr][lc] = pa;
            *(float4*)&Bs[buf ^ 1][lr][lc] = pb;
            __syncthreads();
            buf ^= 1;
        }
    }
#pragma unroll
    for (int i = 0; i < 8; i++) {
        int m = ty * 8 + i;
#pragma unroll
        for (int j = 0; j < 4; j++) {
            int n = n0 + tx * 8 + 2 * j;
            C[(size_t)m * ldc + n]     = lo32(acc[i][j]);
            C[(size_t)m * ldc + n + 1] = hi32(acc[i][j]);
        }
    }
}

// ---------------- GLU + LayerNorm -> trace slot ----------------
__global__ __launch_bounds__(256) void k_glu_ln(const float* __restrict__ syn_b,
                                                const float* __restrict__ ln_g,
                                                const float* __restrict__ ln_b, int slot) {
    int b = blockIdx.x, tid = threadIdx.x;
    __shared__ float sv[DMODEL];
    __shared__ float red[256];
    float s1 = 0.f, s2 = 0.f;
    for (int d = tid; d < DMODEL; d += 256) {
        float za = syn_b[d] + g_z0[b * N1 + d];
        float zb = syn_b[d + DMODEL] + g_z0[b * N1 + DMODEL + d];
#pragma unroll
        for (int s = 0; s < SK1; s++) {
            za += g_zp[(s * BSZ + b) * N1 + d];
            zb += g_zp[(s * BSZ + b) * N1 + DMODEL + d];
        }
        float v = za * sigmoidf_(zb);
        sv[d] = v; s1 += v; s2 += v * v;
    }
    red[tid] = s1; __syncthreads();
    for (int s = 128; s > 0; s >>= 1) { if (tid < s) red[tid] += red[tid + s]; __syncthreads(); }
    float mu = red[0] / (float)DMODEL;
    __syncthreads();
    red[tid] = s2; __syncthreads();
    for (int s = 128; s > 0; s >>= 1) { if (tid < s) red[tid] += red[tid + s]; __syncthreads(); }
    float inv = rsqrtf(red[0] / (float)DMODEL - mu * mu + 1e-5f);
    for (int d = tid; d < DMODEL; d += 256)
        g_trace[(slot * DMODEL + d) * BSZ + b] = (sv[d] - mu) * inv * ln_g[d] + ln_b[d];
}

// ---------------- trace_proc ----------------
__global__ __launch_bounds__(128) void k_traceproc(const float* __restrict__ b1,
                                                   const float* __restrict__ b2, int t) {
    int d = blockIdx.x, b = threadIdx.x;
    __shared__ float ws[MEMN * 64];
    const float* src = g_w1i + d * (MEMN * 64);
    for (int i = b; i < MEMN * 64; i += 128) ws[i] = src[i];
    __syncthreads();
    ULL trp[MEMN];
    int base = (t + 1) % MEMN;
#pragma unroll
    for (int m = 0; m < MEMN; m++) {
        int pm = base + m; if (pm >= MEMN) pm -= MEMN;
        trp[m] = dup2(g_trace[(pm * DMODEL + d) * BSZ + b]);
    }
    const float* b1d = b1 + d * 64;
    const float* w2d = g_w2T + d * 64;
    float o0 = b2[d * 2], o1 = b2[d * 2 + 1];
#pragma unroll
    for (int h2 = 0; h2 < 32; h2 += 2) {
        ULL acc0 = pack2(b1d[h2],     b1d[h2 + 32]);
        ULL acc1 = pack2(b1d[h2 + 1], b1d[h2 + 33]);
        const ULL* wp = ((const ULL*)ws) + h2;
#pragma unroll
        for (int m = 0; m < MEMN; m++) {
            fma2(acc0, trp[m], wp[m * 32]);
            fma2(acc1, trp[m], wp[m * 32 + 1]);
        }
        float h0 = lo32(acc0) * sigmoidf_(hi32(acc0));
        float h1 = lo32(acc1) * sigmoidf_(hi32(acc1));
        o0 += h0 * w2d[h2 * 2]     + h1 * w2d[(h2 + 1) * 2];
        o1 += h0 * w2d[h2 * 2 + 1] + h1 * w2d[(h2 + 1) * 2 + 1];
    }
    float act = o0 * sigmoidf_(o1);
    g_actT[d * BSZ + b] = act;
    tf_store(act, d, b, g_actF);
}

// ---------------- pairwise + alpha + sync ----------------
__global__ __launch_bounds__(256) void k_syncpair(const int* __restrict__ il,
                                                  const int* __restrict__ ir, int t) {
    int p = blockIdx.x * 2 + threadIdx.y;
    int b = threadIdx.x;
    float l  = g_actT[il[g_pi[p]] * BSZ + b];
    float rr = g_actT[ir[g_pj[p]] * BSZ + b];
    float r = g_r[p];
    float a = r * g_alpha[p * BSZ + b] + l * rr;
    g_alpha[p * BSZ + b] = a;
    float beta = 1.0f;
    for (int k = 0; k <= t; k++) beta = r * beta + 1.0f;
    float s = a / sqrtf(beta);
    tf_store(s, p, b, g_syncF);
}

// ---------------- wide split-K reduce + bias + preds ----------------
__global__ __launch_bounds__(256) void k_reduce(const float* __restrict__ outb,
                                                float* __restrict__ dout, int t) {
    int idx = blockIdx.x * 256 + threadIdx.x;
    if (idx >= BSZ * OUTD) return;
    int b = idx / OUTD, n = idx - b * OUTD;
    float v = outb[n];
#pragma unroll
    for (int s = 0; s < SK2; s++) v += g_part[(s * BSZ + b) * OUTD + n];
    g_pred[idx] = v;
    dout[(b * OUTD + n) * NITER + t] = v;
}

// ---------------- entropy / certainty ----------------
__global__ __launch_bounds__(256) void k_finish(float* __restrict__ dout, int t) {
    int b = blockIdx.x, tid = threadIdx.x;
    __shared__ float red[256];
    const float* sp = g_pred + b * OUTD;
    float mx = -3.4e38f;
    for (int n = tid; n < OUTD; n += 256) mx = fmaxf(mx, sp[n]);
    red[tid] = mx; __syncthreads();
    for (int s = 128; s > 0; s >>= 1) { if (tid < s) red[tid] = fmaxf(red[tid], red[tid + s]); __syncthreads(); }
    float smax = red[0];
    __syncthreads();
    float se = 0.f;
    for (int n = tid; n < OUTD; n += 256) se += expf(sp[n] - smax);
    red[tid] = se; __syncthreads();
    for (int s = 128; s > 0; s >>= 1) { if (tid < s) red[tid] += red[tid + s]; __syncthreads(); }
    float lse = smax + logf(red[0]);
    __syncthreads();
    float ent = 0.f;
    for (int n = tid; n < OUTD; n += 256) { float lp = sp[n] - lse; ent += expf(lp) * lp; }
    red[tid] = ent; __syncthreads();
    for (int s = 128; s > 0; s >>= 1) { if (tid < s) red[tid] += red[tid + s]; __syncthreads(); }
    if (tid == 0) {
        float ne = -red[0] / logf(1000.0f);
        dout[CERT_OFF + (b * 2 + 0) * NITER + t] = ne;
        dout[CERT_OFF + (b * 2 + 1) * NITER + t] = 1.0f - ne;
    }
}

// ---------------- host ----------------
extern "C" void kernel_launch(void* const* d_in, const int* in_sizes, int n_in,
                              void* d_out, int out_size) {
    const float* x      = (const float*)d_in[0];
    const float* syn_w  = (const float*)d_in[1];
    const float* syn_b  = (const float*)d_in[2];
    const float* ln_g   = (const float*)d_in[3];
    const float* ln_b   = (const float*)d_in[4];
    const float* tp_w1  = (const float*)d_in[5];
    const float* tp_b1  = (const float*)d_in[6];
    const float* tp_w2  = (const float*)d_in[7];
    const float* tp_b2  = (const float*)d_in[8];
    const float* sas    = (const float*)d_in[9];
    const float* strc   = (const float*)d_in[10];
    const float* decay  = (const float*)d_in[11];
    const float* out_w  = (const float*)d_in[12];
    const float* out_b  = (const float*)d_in[13];
    const int*   il     = (const int*)d_in[14];
    const int*   ir     = (const int*)d_in[15];
    float* out = (float*)d_out;

    float *p_xT, *p_z0, *p_zp, *p_part, *p_synB, *p_outB;
    U32 *p_actF, *p_syncF;
    cudaGetSymbolAddress((void**)&p_xT,    g_xT);
    cudaGetSymbolAddress((void**)&p_z0,    g_z0);
    cudaGetSymbolAddress((void**)&p_zp,    g_zp);
    cudaGetSymbolAddress((void**)&p_part,  g_part);
    cudaGetSymbolAddress((void**)&p_actF,  g_actF);
    cudaGetSymbolAddress((void**)&p_syncF, g_syncF);
    cudaGetSymbolAddress((void**)&p_synB,  g_synB);
    cudaGetSymbolAddress((void**)&p_outB,  g_outB);

    cudaFuncSetAttribute(k_gemm_mma, cudaFuncAttributeMaxDynamicSharedMemorySize, GSMEM);

    // launch order: the first k_gemm_mma is launch #4 (ncu window target)
    k_init_all<<<RTOT / 256, 256>>>(x, strc, sas, tp_w1, tp_w2);
    k_transpose_blk<<<dim3(N1 / TILEN, NKS1), 256>>>(syn_w + (size_t)DIN * N1, N1, NKS1, p_synB);
    k_transpose_blk<<<dim3(OUTPAD / TILEN, NKS2), 256>>>(out_w, OUTD, NKS2, p_outB);

    for (int t = 0; t < NITER; t++) {
        k_gemm_mma<<<dim3(N1 / TILEN, SK1), 256, GSMEM>>>(p_actF, p_synB,
                                                          NKS1, N1, SK1, p_zp, N1);
        if (t == 0) {
            k_gemm_f2<<<N1 / 128, 256>>>(p_xT, syn_w, N1, DIN / 8, p_z0, N1);
            k_init_alpha<<<NSYNC, BSZ>>>(sas, decay, il, ir);
        }
        k_glu_ln<<<BSZ, 256>>>(syn_b, ln_g, ln_b, t % MEMN);
        k_traceproc<<<DMODEL, BSZ>>>(tp_b1, tp_b2, t);
        k_syncpair<<<NSYNC / 2, dim3(BSZ, 2)>>>(il, ir, t);
        k_gemm_mma<<<dim3(OUTPAD / TILEN, SK2), 256, GSMEM>>>(p_syncF, p_outB,
                                                              NKS2, OUTD, SK2, p_part, OUTD);
        k_reduce<<<(BSZ * OUTD + 255) / 256, 256>>>(out_b, out, t);
        k_finish<<<BSZ, 256>>>(out, t);
    }
}

// round 15
// speedup vs baseline: 1.3523x; 1.3523x over previous
#include <cuda_runtime.h>
#include <cuda_bf16.h>
#include <math.h>

#define BSZ    128
#define DIN    512
#define DMODEL 2048
#define MEMN   25
#define NSY    256
#define NSYNC  32896
#define OUTD   1000
#define OUTPAD 1024
#define NITER  24
#define N1     4096
#define SK1    8
#define SK2    36
#define NST    6
#define STFLT  4096                 // floats per B stage (128 rows x 32 k)
#define STBYT  16384
#define GSMEM  (NST * STBYT)        // 98304 bytes dynamic smem
#define NKS1   (DMODEL / 32)        // 64 k32-stages, gemm1
#define NKS2   (NSYNC / 32)         // 1028 k32-stages, gemm2
#define CERT_OFF (BSZ * OUTD * NITER)

// init ranges
#define R1 (DIN * BSZ)
#define R2 (MEMN * DMODEL * BSZ)
#define R3 (DMODEL * BSZ)
#define R4 (MEMN * 64 * DMODEL)
#define R5 (64 * DMODEL)
#define RTOT (R1 + R2 + R3 + R4 + R5)

typedef unsigned long long ULL;
typedef unsigned U32;

// ---------------- persistent scratch ----------------
__device__ float g_trace[MEMN * DMODEL * BSZ];
__device__ float g_actT [DMODEL * BSZ];
__device__ U32   g_actF [DMODEL * BSZ];     // tf32, MMA-fragment-native
__device__ U32   g_syncF[NSYNC * BSZ];
__device__ float g_xT   [DIN * BSZ];
__device__ float g_z0   [BSZ * N1];
__device__ float g_zp   [SK1 * BSZ * N1];
__device__ float g_alpha[NSYNC * BSZ];
__device__ float g_r    [NSYNC];
__device__ int   g_pi   [NSYNC];
__device__ int   g_pj   [NSYNC];
__device__ float g_part [SK2 * BSZ * OUTD];
__device__ float g_pred [BSZ * OUTD];
__device__ float g_w1i  [DMODEL * MEMN * 64];
__device__ float g_w2T  [DMODEL * 64];
// blocked+swizzled B: [n_tile128][k32_stage][128][32]
__device__ float g_synB [(size_t)(N1 / 128) * NKS1 * STFLT];
__device__ float g_outB [(size_t)(OUTPAD / 128) * NKS2 * STFLT];

__device__ __forceinline__ float sigmoidf_(float x) { return 1.0f / (1.0f + expf(-x)); }
__device__ __forceinline__ ULL dup2(float x) {
    ULL r; unsigned u = __float_as_uint(x);
    asm("mov.b64 %0, {%1, %1};" : "=l"(r) : "r"(u)); return r;
}
__device__ __forceinline__ ULL pack2(float lo, float hi) {
    ULL r; asm("mov.b64 %0, {%1, %2};" : "=l"(r) : "r"(__float_as_uint(lo)), "r"(__float_as_uint(hi)));
    return r;
}
__device__ __forceinline__ void fma2(ULL& d, ULL a, ULL b) {
    asm("fma.rn.f32x2 %0, %1, %2, %3;" : "=l"(d) : "l"(a), "l"(b), "l"(d));
}
__device__ __forceinline__ float lo32(ULL v) { return __uint_as_float((unsigned)v); }
__device__ __forceinline__ float hi32(ULL v) { return __uint_as_float((unsigned)(v >> 32)); }

__device__ __forceinline__ U32 f2tf(float v) {
    U32 u; asm("cvt.rna.tf32.f32 %0, %1;" : "=r"(u) : "f"(v)); return u;
}

// Fragment-native tf32 A store (m16n8k8 A-frag; lane's 4 regs contiguous 16B)
__device__ __forceinline__ void tf_store(float v, int k, int m, U32* __restrict__ F) {
    int kb = k >> 3, kc = k & 7, mb = m >> 4, mr = m & 15;
    int lane = (mr & 7) * 4 + (kc & 3);
    int r = ((kc >> 2) << 1) | (mr >> 3);
    F[(kb * 8 + mb) * 128 + lane * 4 + r] = f2tf(v);
}

__device__ __forceinline__ U32 smem_u32(const void* p) {
    U32 a; asm("{ .reg .u64 t; cvta.to.shared.u64 t, %1; cvt.u32.u64 %0, t; }" : "=r"(a) : "l"(p));
    return a;
}
__device__ __forceinline__ void mbar_init(U32 mbar, U32 cnt) {
    asm volatile("mbarrier.init.shared.b64 [%0], %1;" :: "r"(mbar), "r"(cnt) : "memory");
}
__device__ __forceinline__ void mbar_expect_tx(U32 mbar, U32 bytes) {
    asm volatile("mbarrier.arrive.expect_tx.shared.b64 _, [%0], %1;" :: "r"(mbar), "r"(bytes) : "memory");
}
__device__ __forceinline__ void mbar_wait(U32 mbar, U32 parity) {
    asm volatile("{\n\t.reg .pred P;\n\tWL%=:\n\t"
                 "mbarrier.try_wait.parity.acquire.cta.shared::cta.b64 P, [%0], %1, 0x989680;\n\t"
                 "@P bra.uni WD%=;\n\tbra.uni WL%=;\n\tWD%=:\n\t}"
                 :: "r"(mbar), "r"(parity) : "memory");
}
__device__ __forceinline__ void bulk_ld(U32 sdst, const void* g, U32 bytes, U32 mbar) {
    asm volatile("cp.async.bulk.shared::cluster.global.mbarrier::complete_tx::bytes "
                 "[%0], [%1], %2, [%3];"
                 :: "r"(sdst), "l"(g), "r"(bytes), "r"(mbar) : "memory");
}

__device__ __forceinline__ void mma_tf32(float* c, const U32* a, U32 b0, U32 b1) {
    asm volatile("mma.sync.aligned.m16n8k8.row.col.f32.tf32.tf32.f32 "
                 "{%0,%1,%2,%3}, {%4,%5,%6,%7}, {%8,%9}, {%0,%1,%2,%3};"
                 : "+f"(c[0]), "+f"(c[1]), "+f"(c[2]), "+f"(c[3])
                 : "r"(a[0]), "r"(a[1]), "r"(a[2]), "r"(a[3]), "r"(b0), "r"(b1));
}

struct AFrag { uint4 f[2][2]; };

// ks16 = global k16 index
__device__ __forceinline__ void load_afrag(const U32* __restrict__ AF, int ks16, int lane,
                                           int warp_m, AFrag& a) {
#pragma unroll
    for (int kb2 = 0; kb2 < 2; kb2++)
#pragma unroll
        for (int mb2 = 0; mb2 < 2; mb2++)
            a.f[kb2][mb2] = *(const uint4*)(AF +
                (((ks16 * 2 + kb2) * 8 + warp_m * 2 + mb2) * 128 + lane * 4));
}

// 32 MMAs per k16 substep; B from swizzled k32 stage [128][32]
__device__ __forceinline__ void mma_step(float acc[2][8][4], const AFrag& a,
                                         const U32* __restrict__ sBst, int sub,
                                         int warp_n, int lane) {
#pragma unroll
    for (int kb2 = 0; kb2 < 2; kb2++) {
        int kbase = sub * 16 + kb2 * 8 + (lane & 3);
        U32 b[8][2];
#pragma unroll
        for (int j = 0; j < 8; j++) {
            int nn = warp_n * 64 + j * 8 + (lane >> 2);
            int pos = kbase ^ ((nn & 7) << 2);
            b[j][0] = sBst[nn * 32 + pos];
            b[j][1] = sBst[nn * 32 + (pos ^ 4)];
        }
#pragma unroll
        for (int j = 0; j < 8; j++) {
            mma_tf32(acc[0][j], (const U32*)&a.f[kb2][0], b[j][0], b[j][1]);
            mma_tf32(acc[1][j], (const U32*)&a.f[kb2][1], b[j][0], b[j][1]);
        }
    }
}

// ======== TF32 GEMM: k32 bulk stages, mbarrier ring, 2 CTAs/SM ========
__global__ __launch_bounds__(256, 2) void k_gemm_mma(
    const U32* __restrict__ AF, const float* __restrict__ Bblk,
    int nks32, int Nmax, int SK, float* __restrict__ C, int ldc)
{
    extern __shared__ U32 sB[];        // [NST][4096]
    __shared__ ULL mbars[NST];
    int tid = threadIdx.x;
    int lane = tid & 31, wid = tid >> 5;
    int warp_m = wid >> 1, warp_n = wid & 1;
    int n0 = blockIdx.x * 128;
    int z = blockIdx.y;
    int s0 = (int)((long long)z * nks32 / SK);
    int s1 = (int)((long long)(z + 1) * nks32 / SK);
    int nst = s1 - s0;
    const float* Btile = Bblk + (size_t)blockIdx.x * nks32 * STFLT;

    float acc[2][8][4];
#pragma unroll
    for (int i = 0; i < 2; i++)
#pragma unroll
        for (int j = 0; j < 8; j++)
#pragma unroll
            for (int q = 0; q < 4; q++) acc[i][j][q] = 0.0f;

    U32 mb0 = smem_u32(&mbars[0]);
    if (tid == 0) {
#pragma unroll
        for (int s = 0; s < NST; s++) mbar_init(mb0 + s * 8, 1);
    }
    __syncthreads();
    if (tid == 0) {
#pragma unroll
        for (int p = 0; p < 4; p++) {
            if (p < nst) {
                mbar_expect_tx(mb0 + p * 8, STBYT);
                bulk_ld(smem_u32(&sB[p * STFLT]), Btile + (size_t)(s0 + p) * STFLT,
                        STBYT, mb0 + p * 8);
            }
        }
    }
    AFrag a0, a1;
    load_afrag(AF, s0 * 2, lane, warp_m, a0);
    load_afrag(AF, s0 * 2 + 1, lane, warp_m, a1);

    for (int c = 0; c < nst; c++) {
        mbar_wait(mb0 + (c % NST) * 8, (U32)((c / NST) & 1));
        __syncthreads();    // slot-reuse ordering
        if (tid == 0) {
            int cc = c + 4;
            if (cc < nst) {
                int sl = cc % NST;
                mbar_expect_tx(mb0 + sl * 8, STBYT);
                bulk_ld(smem_u32(&sB[sl * STFLT]), Btile + (size_t)(s0 + cc) * STFLT,
                        STBYT, mb0 + sl * 8);
            }
        }
        const U32* st = &sB[(c % NST) * STFLT];
        mma_step(acc, a0, st, 0, warp_n, lane);
        if (c + 1 < nst) load_afrag(AF, (s0 + c + 1) * 2, lane, warp_m, a0);
        mma_step(acc, a1, st, 1, warp_n, lane);
        if (c + 1 < nst) load_afrag(AF, (s0 + c + 1) * 2 + 1, lane, warp_m, a1);
    }

    float* Cz = C + (size_t)z * BSZ * ldc;
#pragma unroll
    for (int i = 0; i < 2; i++) {
        int m0 = warp_m * 32 + i * 16 + (lane >> 2);
#pragma unroll
        for (int j = 0; j < 8; j++) {
            int n = n0 + warp_n * 64 + j * 8 + 2 * (lane & 3);
            if (n < Nmax) {
                Cz[(size_t)m0 * ldc + n]       = acc[i][j][0];
                Cz[(size_t)(m0 + 8) * ldc + n] = acc[i][j][2];
            }
            if (n + 1 < Nmax) {
                Cz[(size_t)m0 * ldc + n + 1]       = acc[i][j][1];
                Cz[(size_t)(m0 + 8) * ldc + n + 1] = acc[i][j][3];
            }
        }
    }
}

// ------- build blocked+swizzled tf32 B: [tile128][k32][128][32] from src[k][ncols] -------
__global__ __launch_bounds__(256) void k_transpose_blk(const float* __restrict__ src, int ncols,
                                                       int nks32, float* __restrict__ dst)
{
    __shared__ float ts[32 * 132];
    int tile = blockIdx.x, ks = blockIdx.y;
    int tid = threadIdx.x;
#pragma unroll
    for (int i = 0; i < 16; i++) {
        int e = i * 256 + tid;          // e = kk*128 + n
        int kk = e >> 7, n = e & 127;
        int col = tile * 128 + n;
        ts[kk * 132 + n] = (col < ncols) ? src[(size_t)(ks * 32 + kk) * ncols + col] : 0.0f;
    }
    __syncthreads();
    float* out = dst + ((size_t)tile * nks32 + ks) * STFLT;
#pragma unroll
    for (int i = 0; i < 16; i++) {
        int o = i * 256 + tid;          // o = nn*32 + pos
        int nn = o >> 5, pos = o & 31;
        int kk = pos ^ ((nn & 7) << 2);
        out[o] = __uint_as_float(f2tf(ts[kk * 132 + nn]));
    }
}

// ---------------- fused init ----------------
__global__ void k_init_all(const float* __restrict__ x, const float* __restrict__ strc,
                           const float* __restrict__ sas, const float* __restrict__ w1,
                           const float* __restrict__ w2) {
    long long idx = blockIdx.x * 256LL + threadIdx.x;
    if (idx < R1) {
        int i = (int)idx;
        g_xT[i] = x[(i & 127) * DIN + (i >> 7)];
        return;
    }
    idx -= R1;
    if (idx < R2) {
        int i = (int)idx;
        int d = (i >> 7) & (DMODEL - 1);
        int m = i >> 18;
        g_trace[i] = strc[d * MEMN + m];
        return;
    }
    idx -= R2;
    if (idx < R3) {
        int i = (int)idx;
        int d = i >> 7, b = i & 127;
        float v = sas[d];
        g_actT[i] = v;
        tf_store(v, d, b, g_actF);
        return;
    }
    idx -= R3;
    if (idx < R4) {
        int i = (int)idx;
        int d = i & (DMODEL - 1);
        int rem = i >> 11;
        int h = rem & 63, m = rem >> 6;
        g_w1i[((d * MEMN + m) * 32 + (h & 31)) * 2 + (h >> 5)] = w1[i];
        return;
    }
    idx -= R4;
    if (idx < R5) {
        int i = (int)idx;
        g_w2T[(i & (DMODEL - 1)) * 64 + (i >> 11)] = w2[i];
    }
}

__global__ void k_init_alpha(const float* __restrict__ sas, const float* __restrict__ decay,
                             const int* __restrict__ il, const int* __restrict__ ir) {
    int p = blockIdx.x, b = threadIdx.x;
    float pf = (float)p;
    int i = (int)floorf(256.5f - sqrtf(256.5f * 256.5f - 2.0f * pf));
    if (i < 0) i = 0;
    if (i > NSY - 1) i = NSY - 1;
    while (i > 0 && (i * NSY - i * (i - 1) / 2) > p) i--;
    while (i < NSY - 1 && ((i + 1) * NSY - (i + 1) * i / 2) <= p) i++;
    int j = i + (p - (i * NSY - i * (i - 1) / 2));
    if (b == 0) {
        g_pi[p] = i; g_pj[p] = j;
        g_r[p] = expf(-fminf(fmaxf(decay[p], 0.0f), 15.0f));
    }
    g_alpha[p * BSZ + b] = sas[il[i]] * sas[ir[j]];
}

// ---------------- FMA2 GEMM (one-time z0 = x @ W_top, exact fp32) ----------------
__global__ __launch_bounds__(256) void k_gemm_f2(
    const float* __restrict__ A, const float* __restrict__ B,
    int ldb, int nkb, float* __restrict__ C, int ldc)
{
    __shared__ float As[2][8][128];
    __shared__ float Bs[2][8][128];
    int n0 = blockIdx.x * 128;
    int tid = threadIdx.x;
    int lr = tid >> 5, lc = (tid & 31) * 4;
    int ty = tid >> 4, tx = tid & 15;
    ULL acc[8][4];
#pragma unroll
    for (int i = 0; i < 8; i++)
#pragma unroll
        for (int j = 0; j < 4; j++) acc[i][j] = 0ULL;
    float4 pa = *(const float4*)(A + lr * BSZ + lc);
    float4 pb = *(const float4*)(B + (size_t)lr * ldb + n0 + lc);
    *(float4*)&As[0][lr][lc] = pa;
    *(float4*)&Bs[0][lr][lc] = pb;
    __syncthreads();
    int buf = 0;
    for (int kb = 0; kb < nkb; kb++) {
        bool has = (kb + 1 < nkb);
        if (has) {
            int krow = (kb + 1) * 8 + lr;
            pa = *(const float4*)(A + krow * BSZ + lc);
            pb = *(const float4*)(B + (size_t)krow * ldb + n0 + lc);
        }
#pragma unroll
        for (int kk = 0; kk < 8; kk++) {
            float a[8];
            *(float4*)&a[0] = *(const float4*)&As[buf][kk][ty * 8];
            *(float4*)&a[4] = *(const float4*)&As[buf][kk][ty * 8 + 4];
            ULL bv[4];
            const ULL* bp = (const ULL*)&Bs[buf][kk][tx * 8];
#pragma unroll
            for (int j = 0; j < 4; j++) bv[j] = bp[j];
#pragma unroll
            for (int i = 0; i < 8; i++) {
                ULL ad = dup2(a[i]);
#pragma unroll
                for (int j = 0; j < 4; j++) fma2(acc[i][j], ad, bv[j]);
            }
        }
        if (has) {
            *(float4*)&As[buf ^ 1][lr][lc] = pa;
            *(float4*)&Bs[buf ^ 1][lr][lc] = pb;
            __syncthreads();
            buf ^= 1;
        }
    }
#pragma unroll
    for (int i = 0; i < 8; i++) {
        int m = ty * 8 + i;
#pragma unroll
        for (int j = 0; j < 4; j++) {
            int n = n0 + tx * 8 + 2 * j;
            C[(size_t)m * ldc + n]     = lo32(acc[i][j]);
            C[(size_t)m * ldc + n + 1] = hi32(acc[i][j]);
        }
    }
}

// ---------------- GLU + LayerNorm -> trace slot ----------------
__global__ __launch_bounds__(256) void k_glu_ln(const float* __restrict__ syn_b,
                                                const float* __restrict__ ln_g,
                                                const float* __restrict__ ln_b, int slot) {
    int b = blockIdx.x, tid = threadIdx.x;
    __shared__ float sv[DMODEL];
    __shared__ float red[256];
    float s1 = 0.f, s2 = 0.f;
    for (int d = tid; d < DMODEL; d += 256) {
        float za = syn_b[d] + g_z0[b * N1 + d];
        float zb = syn_b[d + DMODEL] + g_z0[b * N1 + DMODEL + d];
#pragma unroll
        for (int s = 0; s < SK1; s++) {
            za += g_zp[(s * BSZ + b) * N1 + d];
            zb += g_zp[(s * BSZ + b) * N1 + DMODEL + d];
        }
        float v = za * sigmoidf_(zb);
        sv[d] = v; s1 += v; s2 += v * v;
    }
    red[tid] = s1; __syncthreads();
    for (int s = 128; s > 0; s >>= 1) { if (tid < s) red[tid] += red[tid + s]; __syncthreads(); }
    float mu = red[0] / (float)DMODEL;
    __syncthreads();
    red[tid] = s2; __syncthreads();
    for (int s = 128; s > 0; s >>= 1) { if (tid < s) red[tid] += red[tid + s]; __syncthreads(); }
    float inv = rsqrtf(red[0] / (float)DMODEL - mu * mu + 1e-5f);
    for (int d = tid; d < DMODEL; d += 256)
        g_trace[(slot * DMODEL + d) * BSZ + b] = (sv[d] - mu) * inv * ln_g[d] + ln_b[d];
}

// ---------------- trace_proc ----------------
__global__ __launch_bounds__(128) void k_traceproc(const float* __restrict__ b1,
                                                   const float* __restrict__ b2, int t) {
    int d = blockIdx.x, b = threadIdx.x;
    __shared__ float ws[MEMN * 64];
    const float* src = g_w1i + d * (MEMN * 64);
    for (int i = b; i < MEMN * 64; i += 128) ws[i] = src[i];
    __syncthreads();
    ULL trp[MEMN];
    int base = (t + 1) % MEMN;
#pragma unroll
    for (int m = 0; m < MEMN; m++) {
        int pm = base + m; if (pm >= MEMN) pm -= MEMN;
        trp[m] = dup2(g_trace[(pm * DMODEL + d) * BSZ + b]);
    }
    const float* b1d = b1 + d * 64;
    const float* w2d = g_w2T + d * 64;
    float o0 = b2[d * 2], o1 = b2[d * 2 + 1];
#pragma unroll
    for (int h2 = 0; h2 < 32; h2 += 2) {
        ULL acc0 = pack2(b1d[h2],     b1d[h2 + 32]);
        ULL acc1 = pack2(b1d[h2 + 1], b1d[h2 + 33]);
        const ULL* wp = ((const ULL*)ws) + h2;
#pragma unroll
        for (int m = 0; m < MEMN; m++) {
            fma2(acc0, trp[m], wp[m * 32]);
            fma2(acc1, trp[m], wp[m * 32 + 1]);
        }
        float h0 = lo32(acc0) * sigmoidf_(hi32(acc0));
        float h1 = lo32(acc1) * sigmoidf_(hi32(acc1));
        o0 += h0 * w2d[h2 * 2]     + h1 * w2d[(h2 + 1) * 2];
        o1 += h0 * w2d[h2 * 2 + 1] + h1 * w2d[(h2 + 1) * 2 + 1];
    }
    float act = o0 * sigmoidf_(o1);
    g_actT[d * BSZ + b] = act;
    tf_store(act, d, b, g_actF);
}

// ---------------- pairwise + alpha + sync ----------------
__global__ __launch_bounds__(256) void k_syncpair(const int* __restrict__ il,
                                                  const int* __restrict__ ir, int t) {
    int p = blockIdx.x * 2 + threadIdx.y;
    int b = threadIdx.x;
    float l  = g_actT[il[g_pi[p]] * BSZ + b];
    float rr = g_actT[ir[g_pj[p]] * BSZ + b];
    float r = g_r[p];
    float a = r * g_alpha[p * BSZ + b] + l * rr;
    g_alpha[p * BSZ + b] = a;
    float beta = 1.0f;
    for (int k = 0; k <= t; k++) beta = r * beta + 1.0f;
    float s = a / sqrtf(beta);
    tf_store(s, p, b, g_syncF);
}

// ---------------- wide split-K reduce + bias + preds ----------------
__global__ __launch_bounds__(256) void k_reduce(const float* __restrict__ outb,
                                                float* __restrict__ dout, int t) {
    int idx = blockIdx.x * 256 + threadIdx.x;
    if (idx >= BSZ * OUTD) return;
    int b = idx / OUTD, n = idx - b * OUTD;
    float v = outb[n];
#pragma unroll
    for (int s = 0; s < SK2; s++) v += g_part[(s * BSZ + b) * OUTD + n];
    g_pred[idx] = v;
    dout[(b * OUTD + n) * NITER + t] = v;
}

// ---------------- entropy / certainty ----------------
__global__ __launch_bounds__(256) void k_finish(float* __restrict__ dout, int t) {
    int b = blockIdx.x, tid = threadIdx.x;
    __shared__ float red[256];
    const float* sp = g_pred + b * OUTD;
    float mx = -3.4e38f;
    for (int n = tid; n < OUTD; n += 256) mx = fmaxf(mx, sp[n]);
    red[tid] = mx; __syncthreads();
    for (int s = 128; s > 0; s >>= 1) { if (tid < s) red[tid] = fmaxf(red[tid], red[tid + s]); __syncthreads(); }
    float smax = red[0];
    __syncthreads();
    float se = 0.f;
    for (int n = tid; n < OUTD; n += 256) se += expf(sp[n] - smax);
    red[tid] = se; __syncthreads();
    for (int s = 128; s > 0; s >>= 1) { if (tid < s) red[tid] += red[tid + s]; __syncthreads(); }
    float lse = smax + logf(red[0]);
    __syncthreads();
    float ent = 0.f;
    for (int n = tid; n < OUTD; n += 256) { float lp = sp[n] - lse; ent += expf(lp) * lp; }
    red[tid] = ent; __syncthreads();
    for (int s = 128; s > 0; s >>= 1) { if (tid < s) red[tid] += red[tid + s]; __syncthreads(); }
    if (tid == 0) {
        float ne = -red[0] / logf(1000.0f);
        dout[CERT_OFF + (b * 2 + 0) * NITER + t] = ne;
        dout[CERT_OFF + (b * 2 + 1) * NITER + t] = 1.0f - ne;
    }
}

// ---------------- host ----------------
extern "C" void kernel_launch(void* const* d_in, const int* in_sizes, int n_in,
                              void* d_out, int out_size) {
    const float* x      = (const float*)d_in[0];
    const float* syn_w  = (const float*)d_in[1];
    const float* syn_b  = (const float*)d_in[2];
    const float* ln_g   = (const float*)d_in[3];
    const float* ln_b   = (const float*)d_in[4];
    const float* tp_w1  = (const float*)d_in[5];
    const float* tp_b1  = (const float*)d_in[6];
    const float* tp_w2  = (const float*)d_in[7];
    const float* tp_b2  = (const float*)d_in[8];
    const float* sas    = (const float*)d_in[9];
    const float* strc   = (const float*)d_in[10];
    const float* decay  = (const float*)d_in[11];
    const float* out_w  = (const float*)d_in[12];
    const float* out_b  = (const float*)d_in[13];
    const int*   il     = (const int*)d_in[14];
    const int*   ir     = (const int*)d_in[15];
    float* out = (float*)d_out;

    float *p_xT, *p_z0, *p_zp, *p_part, *p_synB, *p_outB;
    U32 *p_actF, *p_syncF;
    cudaGetSymbolAddress((void**)&p_xT,    g_xT);
    cudaGetSymbolAddress((void**)&p_z0,    g_z0);
    cudaGetSymbolAddress((void**)&p_zp,    g_zp);
    cudaGetSymbolAddress((void**)&p_part,  g_part);
    cudaGetSymbolAddress((void**)&p_actF,  g_actF);
    cudaGetSymbolAddress((void**)&p_syncF, g_syncF);
    cudaGetSymbolAddress((void**)&p_synB,  g_synB);
    cudaGetSymbolAddress((void**)&p_outB,  g_outB);

    cudaFuncSetAttribute(k_gemm_mma, cudaFuncAttributeMaxDynamicSharedMemorySize, GSMEM);

    // launch order: the first k_gemm_mma is launch #4 (ncu window target)
    k_init_all<<<RTOT / 256, 256>>>(x, strc, sas, tp_w1, tp_w2);
    k_transpose_blk<<<dim3(N1 / 128, NKS1), 256>>>(syn_w + (size_t)DIN * N1, N1, NKS1, p_synB);
    k_transpose_blk<<<dim3(OUTPAD / 128, NKS2), 256>>>(out_w, OUTD, NKS2, p_outB);

    for (int t = 0; t < NITER; t++) {
        k_gemm_mma<<<dim3(N1 / 128, SK1), 256, GSMEM>>>(p_actF, p_synB,
                                                        NKS1, N1, SK1, p_zp, N1);
        if (t == 0) {
            k_gemm_f2<<<N1 / 128, 256>>>(p_xT, syn_w, N1, DIN / 8, p_z0, N1);
            k_init_alpha<<<NSYNC, BSZ>>>(sas, decay, il, ir);
        }
        k_glu_ln<<<BSZ, 256>>>(syn_b, ln_g, ln_b, t % MEMN);
        k_traceproc<<<DMODEL, BSZ>>>(tp_b1, tp_b2, t);
        k_syncpair<<<NSYNC / 2, dim3(BSZ, 2)>>>(il, ir, t);
        k_gemm_mma<<<dim3(OUTPAD / 128, SK2), 256, GSMEM>>>(p_syncF, p_outB,
                                                            NKS2, OUTD, SK2, p_part, OUTD);
        k_reduce<<<(BSZ * OUTD + 255) / 256, 256>>>(out_b, out, t);
        k_finish<<<BSZ, 256>>>(out, t);
    }
}

// round 16
// speedup vs baseline: 1.4615x; 1.0808x over previous
#include <cuda_runtime.h>
#include <cuda_bf16.h>
#include <math.h>

#define BSZ    128
#define DIN    512
#define DMODEL 2048
#define MEMN   25
#define NSY    256
#define NSYNC  32896
#define OUTD   1000
#define OUTPAD 1024
#define NITER  24
#define N1     4096
#define SK1    8
#define SK2    36
#define NST    6
#define STFLT  2048                 // floats per B stage (128 rows x 16 k)
#define STBYT  8192
#define GSMEM  (NST * STBYT)        // 49152 bytes dynamic smem
#define NKS1   (DMODEL / 16)        // 128 stages, gemm1
#define NKS2   (NSYNC / 16)         // 2056 stages, gemm2
#define CERT_OFF (BSZ * OUTD * NITER)

// init ranges
#define R1 (DIN * BSZ)
#define R2 (MEMN * DMODEL * BSZ)
#define R3 (DMODEL * BSZ)
#define R4 (MEMN * 64 * DMODEL)
#define R5 (64 * DMODEL)
#define RTOT (R1 + R2 + R3 + R4 + R5)

typedef unsigned long long ULL;
typedef unsigned U32;

// ---------------- persistent scratch ----------------
__device__ float g_trace[MEMN * DMODEL * BSZ];
__device__ float g_actT [DMODEL * BSZ];
__device__ U32   g_actF [DMODEL * BSZ];     // tf32, MMA-fragment-native
__device__ U32   g_syncF[NSYNC * BSZ];
__device__ float g_xT   [DIN * BSZ];
__device__ float g_z0   [BSZ * N1];
__device__ float g_zp   [SK1 * BSZ * N1];
__device__ float g_alpha[NSYNC * BSZ];
__device__ float g_r    [NSYNC];
__device__ int   g_pi   [NSYNC];
__device__ int   g_pj   [NSYNC];
__device__ float g_part [SK2 * BSZ * OUTD];
__device__ float g_pred [BSZ * OUTD];
__device__ float g_w1i  [DMODEL * MEMN * 64];
__device__ float g_w2T  [DMODEL * 64];
// blocked+swizzled B: [n_tile][k_stage][128][16]
__device__ float g_synB [(size_t)(N1 / 128) * NKS1 * STFLT];
__device__ float g_outB [(size_t)(OUTPAD / 128) * NKS2 * STFLT];

__device__ __forceinline__ float sigmoidf_(float x) { return 1.0f / (1.0f + expf(-x)); }
__device__ __forceinline__ ULL dup2(float x) {
    ULL r; unsigned u = __float_as_uint(x);
    asm("mov.b64 %0, {%1, %1};" : "=l"(r) : "r"(u)); return r;
}
__device__ __forceinline__ ULL pack2(float lo, float hi) {
    ULL r; asm("mov.b64 %0, {%1, %2};" : "=l"(r) : "r"(__float_as_uint(lo)), "r"(__float_as_uint(hi)));
    return r;
}
__device__ __forceinline__ void fma2(ULL& d, ULL a, ULL b) {
    asm("fma.rn.f32x2 %0, %1, %2, %3;" : "=l"(d) : "l"(a), "l"(b), "l"(d));
}
__device__ __forceinline__ float lo32(ULL v) { return __uint_as_float((unsigned)v); }
__device__ __forceinline__ float hi32(ULL v) { return __uint_as_float((unsigned)(v >> 32)); }

__device__ __forceinline__ U32 f2tf(float v) {
    U32 u; asm("cvt.rna.tf32.f32 %0, %1;" : "=r"(u) : "f"(v)); return u;
}

// Fragment-native tf32 A store (m16n8k8 A-frag; lane's 4 regs contiguous 16B)
__device__ __forceinline__ void tf_store(float v, int k, int m, U32* __restrict__ F) {
    int kb = k >> 3, kc = k & 7, mb = m >> 4, mr = m & 15;
    int lane = (mr & 7) * 4 + (kc & 3);
    int r = ((kc >> 2) << 1) | (mr >> 3);
    F[(kb * 8 + mb) * 128 + lane * 4 + r] = f2tf(v);
}

__device__ __forceinline__ U32 smem_u32(const void* p) {
    U32 a; asm("{ .reg .u64 t; cvta.to.shared.u64 t, %1; cvt.u32.u64 %0, t; }" : "=r"(a) : "l"(p));
    return a;
}
__device__ __forceinline__ void mbar_init(U32 mbar, U32 cnt) {
    asm volatile("mbarrier.init.shared.b64 [%0], %1;" :: "r"(mbar), "r"(cnt) : "memory");
}
__device__ __forceinline__ void mbar_expect_tx(U32 mbar, U32 bytes) {
    asm volatile("mbarrier.arrive.expect_tx.shared.b64 _, [%0], %1;" :: "r"(mbar), "r"(bytes) : "memory");
}
__device__ __forceinline__ void mbar_wait(U32 mbar, U32 parity) {
    asm volatile("{\n\t.reg .pred P;\n\tWL%=:\n\t"
                 "mbarrier.try_wait.parity.acquire.cta.shared::cta.b64 P, [%0], %1, 0x989680;\n\t"
                 "@P bra.uni WD%=;\n\tbra.uni WL%=;\n\tWD%=:\n\t}"
                 :: "r"(mbar), "r"(parity) : "memory");
}
__device__ __forceinline__ void bulk_ld(U32 sdst, const void* g, U32 bytes, U32 mbar) {
    asm volatile("cp.async.bulk.shared::cluster.global.mbarrier::complete_tx::bytes "
                 "[%0], [%1], %2, [%3];"
                 :: "r"(sdst), "l"(g), "r"(bytes), "r"(mbar) : "memory");
}

__device__ __forceinline__ void mma_tf32(float* c, const U32* a, U32 b0, U32 b1) {
    asm volatile("mma.sync.aligned.m16n8k8.row.col.f32.tf32.tf32.f32 "
                 "{%0,%1,%2,%3}, {%4,%5,%6,%7}, {%8,%9}, {%0,%1,%2,%3};"
                 : "+f"(c[0]), "+f"(c[1]), "+f"(c[2]), "+f"(c[3])
                 : "r"(a[0]), "r"(a[1]), "r"(a[2]), "r"(a[3]), "r"(b0), "r"(b1));
}

struct AFrag { uint4 f[2][2]; };

__device__ __forceinline__ void load_afrag(const U32* __restrict__ AF, int ks, int lane,
                                           int warp_m, AFrag& a) {
#pragma unroll
    for (int kb2 = 0; kb2 < 2; kb2++)
#pragma unroll
        for (int mb2 = 0; mb2 < 2; mb2++)
            a.f[kb2][mb2] = *(const uint4*)(AF +
                (((ks * 2 + kb2) * 8 + warp_m * 2 + mb2) * 128 + lane * 4));
}

// 32 MMAs per k16 stage; B from swizzled blocked stage [128][16]
__device__ __forceinline__ void mma_step(float acc[2][8][4], const AFrag& a,
                                         const U32* __restrict__ sB, int warp_n, int lane) {
#pragma unroll
    for (int kb2 = 0; kb2 < 2; kb2++) {
        U32 b[8][2];
#pragma unroll
        for (int j = 0; j < 8; j++) {
            int nn = warp_n * 64 + j * 8 + (lane >> 2);
            int sw = ((nn >> 1) & 3) << 2;
            int pos = (kb2 * 8 + (lane & 3)) ^ sw;
            b[j][0] = sB[nn * 16 + pos];
            b[j][1] = sB[nn * 16 + (pos ^ 4)];
        }
#pragma unroll
        for (int j = 0; j < 8; j++) {
            mma_tf32(acc[0][j], (const U32*)&a.f[kb2][0], b[j][0], b[j][1]);
            mma_tf32(acc[1][j], (const U32*)&a.f[kb2][1], b[j][0], b[j][1]);
        }
    }
}

// ======== TF32 GEMM: cp.async.bulk B stages + mbarrier ring, 2 CTAs/SM ========
__global__ __launch_bounds__(256, 2) void k_gemm_mma(
    const U32* __restrict__ AF, const float* __restrict__ Bblk,
    int nksTot, int Nmax, int SK, float* __restrict__ C, int ldc)
{
    extern __shared__ U32 sB[];        // [NST][2048]
    __shared__ ULL mbars[NST];
    int tid = threadIdx.x;
    int lane = tid & 31, wid = tid >> 5;
    int warp_m = wid >> 1, warp_n = wid & 1;
    int n0 = blockIdx.x * 128;
    int z = blockIdx.y;
    int s0 = (int)((long long)z * nksTot / SK);
    int s1 = (int)((long long)(z + 1) * nksTot / SK);
    int nst = s1 - s0;
    const float* Btile = Bblk + (size_t)blockIdx.x * nksTot * STFLT;

    float acc[2][8][4];
#pragma unroll
    for (int i = 0; i < 2; i++)
#pragma unroll
        for (int j = 0; j < 8; j++)
#pragma unroll
            for (int q = 0; q < 4; q++) acc[i][j][q] = 0.0f;

    U32 mb0 = smem_u32(&mbars[0]);
    if (tid == 0) {
#pragma unroll
        for (int s = 0; s < NST; s++) mbar_init(mb0 + s * 8, 1);
    }
    __syncthreads();
    if (tid == 0) {
#pragma unroll
        for (int p = 0; p < 4; p++) {
            if (p < nst) {
                mbar_expect_tx(mb0 + p * 8, STBYT);
                bulk_ld(smem_u32(&sB[p * STFLT]), Btile + (size_t)(s0 + p) * STFLT,
                        STBYT, mb0 + p * 8);
            }
        }
    }
    AFrag a0, a1;
    load_afrag(AF, s0, lane, warp_m, a0);
    if (nst > 1) load_afrag(AF, s0 + 1, lane, warp_m, a1);

    for (int c = 0; c < nst; c += 2) {
        mbar_wait(mb0 + (c % NST) * 8, (U32)((c / NST) & 1));
        if (c + 1 < nst) mbar_wait(mb0 + ((c + 1) % NST) * 8, (U32)(((c + 1) / NST) & 1));
        __syncthreads();    // slot-reuse ordering: all warps done with pair c-2
        if (tid == 0) {
#pragma unroll
            for (int u = 0; u < 2; u++) {
                int cc = c + 4 + u;
                if (cc < nst) {
                    int sl = cc % NST;
                    mbar_expect_tx(mb0 + sl * 8, STBYT);
                    bulk_ld(smem_u32(&sB[sl * STFLT]), Btile + (size_t)(s0 + cc) * STFLT,
                            STBYT, mb0 + sl * 8);
                }
            }
        }
        mma_step(acc, a0, &sB[(c % NST) * STFLT], warp_n, lane);
        if (c + 2 < nst) load_afrag(AF, s0 + c + 2, lane, warp_m, a0);
        if (c + 1 < nst) {
            mma_step(acc, a1, &sB[((c + 1) % NST) * STFLT], warp_n, lane);
            if (c + 3 < nst) load_afrag(AF, s0 + c + 3, lane, warp_m, a1);
        }
    }

    float* Cz = C + (size_t)z * BSZ * ldc;
#pragma unroll
    for (int i = 0; i < 2; i++) {
        int m0 = warp_m * 32 + i * 16 + (lane >> 2);
#pragma unroll
        for (int j = 0; j < 8; j++) {
            int n = n0 + warp_n * 64 + j * 8 + 2 * (lane & 3);
            if (n < Nmax) {
                Cz[(size_t)m0 * ldc + n]       = acc[i][j][0];
                Cz[(size_t)(m0 + 8) * ldc + n] = acc[i][j][2];
            }
            if (n + 1 < Nmax) {
                Cz[(size_t)m0 * ldc + n + 1]       = acc[i][j][1];
                Cz[(size_t)(m0 + 8) * ldc + n + 1] = acc[i][j][3];
            }
        }
    }
}

// ------- build blocked+swizzled tf32 B: [tile][stage][128][16] from src[k][ncols] -------
__global__ __launch_bounds__(256) void k_transpose_blk(const float* __restrict__ src, int ncols,
                                                       int nksTot, float* __restrict__ dst)
{
    __shared__ float ts[16 * 132];
    int tile = blockIdx.x, ks = blockIdx.y;
    int tid = threadIdx.x;
#pragma unroll
    for (int i = 0; i < 8; i++) {
        int e = i * 256 + tid;          // e = kk*128 + n
        int kk = e >> 7, n = e & 127;
        int col = tile * 128 + n;
        ts[kk * 132 + n] = (col < ncols) ? src[(size_t)(ks * 16 + kk) * ncols + col] : 0.0f;
    }
    __syncthreads();
    float* out = dst + ((size_t)tile * nksTot + ks) * STFLT;
#pragma unroll
    for (int i = 0; i < 8; i++) {
        int o = i * 256 + tid;          // o = r*16 + kpos
        int r = o >> 4, kpos = o & 15;
        int kk = kpos ^ (((r >> 1) & 3) << 2);
        out[o] = __uint_as_float(f2tf(ts[kk * 132 + r]));
    }
}

// ---------------- fused init ----------------
__global__ void k_init_all(const float* __restrict__ x, const float* __restrict__ strc,
                           const float* __restrict__ sas, const float* __restrict__ w1,
                           const float* __restrict__ w2) {
    long long idx = blockIdx.x * 256LL + threadIdx.x;
    if (idx < R1) {
        int i = (int)idx;
        g_xT[i] = x[(i & 127) * DIN + (i >> 7)];
        return;
    }
    idx -= R1;
    if (idx < R2) {
        int i = (int)idx;
        int d = (i >> 7) & (DMODEL - 1);
        int m = i >> 18;
        g_trace[i] = strc[d * MEMN + m];
        return;
    }
    idx -= R2;
    if (idx < R3) {
        int i = (int)idx;
        int d = i >> 7, b = i & 127;
        float v = sas[d];
        g_actT[i] = v;
        tf_store(v, d, b, g_actF);
        return;
    }
    idx -= R3;
    if (idx < R4) {
        int i = (int)idx;
        int d = i & (DMODEL - 1);
        int rem = i >> 11;
        int h = rem & 63, m = rem >> 6;
        g_w1i[((d * MEMN + m) * 32 + (h & 31)) * 2 + (h >> 5)] = w1[i];
        return;
    }
    idx -= R4;
    if (idx < R5) {
        int i = (int)idx;
        g_w2T[(i & (DMODEL - 1)) * 64 + (i >> 11)] = w2[i];
    }
}

__global__ void k_init_alpha(const float* __restrict__ sas, const float* __restrict__ decay,
                             const int* __restrict__ il, const int* __restrict__ ir) {
    int p = blockIdx.x, b = threadIdx.x;
    float pf = (float)p;
    int i = (int)floorf(256.5f - sqrtf(256.5f * 256.5f - 2.0f * pf));
    if (i < 0) i = 0;
    if (i > NSY - 1) i = NSY - 1;
    while (i > 0 && (i * NSY - i * (i - 1) / 2) > p) i--;
    while (i < NSY - 1 && ((i + 1) * NSY - (i + 1) * i / 2) <= p) i++;
    int j = i + (p - (i * NSY - i * (i - 1) / 2));
    if (b == 0) {
        g_pi[p] = i; g_pj[p] = j;
        g_r[p] = expf(-fminf(fmaxf(decay[p], 0.0f), 15.0f));
    }
    g_alpha[p * BSZ + b] = sas[il[i]] * sas[ir[j]];
}

// ---------------- FMA2 GEMM (one-time z0 = x @ W_top, exact fp32) ----------------
__global__ __launch_bounds__(256) void k_gemm_f2(
    const float* __restrict__ A, const float* __restrict__ B,
    int ldb, int nkb, float* __restrict__ C, int ldc)
{
    __shared__ float As[2][8][128];
    __shared__ float Bs[2][8][128];
    int n0 = blockIdx.x * 128;
    int tid = threadIdx.x;
    int lr = tid >> 5, lc = (tid & 31) * 4;
    int ty = tid >> 4, tx = tid & 15;
    ULL acc[8][4];
#pragma unroll
    for (int i = 0; i < 8; i++)
#pragma unroll
        for (int j = 0; j < 4; j++) acc[i][j] = 0ULL;
    float4 pa = *(const float4*)(A + lr * BSZ + lc);
    float4 pb = *(const float4*)(B + (size_t)lr * ldb + n0 + lc);
    *(float4*)&As[0][lr][lc] = pa;
    *(float4*)&Bs[0][lr][lc] = pb;
    __syncthreads();
    int buf = 0;
    for (int kb = 0; kb < nkb; kb++) {
        bool has = (kb + 1 < nkb);
        if (has) {
            int krow = (kb + 1) * 8 + lr;
            pa = *(const float4*)(A + krow * BSZ + lc);
            pb = *(const float4*)(B + (size_t)krow * ldb + n0 + lc);
        }
#pragma unroll
        for (int kk = 0; kk < 8; kk++) {
            float a[8];
            *(float4*)&a[0] = *(const float4*)&As[buf][kk][ty * 8];
            *(float4*)&a[4] = *(const float4*)&As[buf][kk][ty * 8 + 4];
            ULL bv[4];
            const ULL* bp = (const ULL*)&Bs[buf][kk][tx * 8];
#pragma unroll
            for (int j = 0; j < 4; j++) bv[j] = bp[j];
#pragma unroll
            for (int i = 0; i < 8; i++) {
                ULL ad = dup2(a[i]);
#pragma unroll
                for (int j = 0; j < 4; j++) fma2(acc[i][j], ad, bv[j]);
            }
        }
        if (has) {
            *(float4*)&As[buf ^ 1][lr][lc] = pa;
            *(float4*)&Bs[buf ^ 1][lr][lc] = pb;
            __syncthreads();
            buf ^= 1;
        }
    }
#pragma unroll
    for (int i = 0; i < 8; i++) {
        int m = ty * 8 + i;
#pragma unroll
        for (int j = 0; j < 4; j++) {
            int n = n0 + tx * 8 + 2 * j;
            C[(size_t)m * ldc + n]     = lo32(acc[i][j]);
            C[(size_t)m * ldc + n + 1] = hi32(acc[i][j]);
        }
    }
}

// ---------------- GLU + LayerNorm -> trace slot ----------------
__global__ __launch_bounds__(256) void k_glu_ln(const float* __restrict__ syn_b,
                                                const float* __restrict__ ln_g,
                                                const float* __restrict__ ln_b, int slot) {
    int b = blockIdx.x, tid = threadIdx.x;
    __shared__ float sv[DMODEL];
    __shared__ float red[256];
    float s1 = 0.f, s2 = 0.f;
    for (int d = tid; d < DMODEL; d += 256) {
        float za = syn_b[d] + g_z0[b * N1 + d];
        float zb = syn_b[d + DMODEL] + g_z0[b * N1 + DMODEL + d];
#pragma unroll
        for (int s = 0; s < SK1; s++) {
            za += g_zp[(s * BSZ + b) * N1 + d];
            zb += g_zp[(s * BSZ + b) * N1 + DMODEL + d];
        }
        float v = za * sigmoidf_(zb);
        sv[d] = v; s1 += v; s2 += v * v;
    }
    red[tid] = s1; __syncthreads();
    for (int s = 128; s > 0; s >>= 1) { if (tid < s) red[tid] += red[tid + s]; __syncthreads(); }
    float mu = red[0] / (float)DMODEL;
    __syncthreads();
    red[tid] = s2; __syncthreads();
    for (int s = 128; s > 0; s >>= 1) { if (tid < s) red[tid] += red[tid + s]; __syncthreads(); }
    float inv = rsqrtf(red[0] / (float)DMODEL - mu * mu + 1e-5f);
    for (int d = tid; d < DMODEL; d += 256)
        g_trace[(slot * DMODEL + d) * BSZ + b] = (sv[d] - mu) * inv * ln_g[d] + ln_b[d];
}

// ---------------- trace_proc ----------------
__global__ __launch_bounds__(128) void k_traceproc(const float* __restrict__ b1,
                                                   const float* __restrict__ b2, int t) {
    int d = blockIdx.x, b = threadIdx.x;
    __shared__ float ws[MEMN * 64];
    const float* src = g_w1i + d * (MEMN * 64);
    for (int i = b; i < MEMN * 64; i += 128) ws[i] = src[i];
    __syncthreads();
    ULL trp[MEMN];
    int base = (t + 1) % MEMN;
#pragma unroll
    for (int m = 0; m < MEMN; m++) {
        int pm = base + m; if (pm >= MEMN) pm -= MEMN;
        trp[m] = dup2(g_trace[(pm * DMODEL + d) * BSZ + b]);
    }
    const float* b1d = b1 + d * 64;
    const float* w2d = g_w2T + d * 64;
    float o0 = b2[d * 2], o1 = b2[d * 2 + 1];
#pragma unroll
    for (int h2 = 0; h2 < 32; h2 += 2) {
        ULL acc0 = pack2(b1d[h2],     b1d[h2 + 32]);
        ULL acc1 = pack2(b1d[h2 + 1], b1d[h2 + 33]);
        const ULL* wp = ((const ULL*)ws) + h2;
#pragma unroll
        for (int m = 0; m < MEMN; m++) {
            fma2(acc0, trp[m], wp[m * 32]);
            fma2(acc1, trp[m], wp[m * 32 + 1]);
        }
        float h0 = lo32(acc0) * sigmoidf_(hi32(acc0));
        float h1 = lo32(acc1) * sigmoidf_(hi32(acc1));
        o0 += h0 * w2d[h2 * 2]     + h1 * w2d[(h2 + 1) * 2];
        o1 += h0 * w2d[h2 * 2 + 1] + h1 * w2d[(h2 + 1) * 2 + 1];
    }
    float act = o0 * sigmoidf_(o1);
    g_actT[d * BSZ + b] = act;
    tf_store(act, d, b, g_actF);
}

// ---------------- pairwise + alpha + sync ----------------
__global__ __launch_bounds__(256) void k_syncpair(const int* __restrict__ il,
                                                  const int* __restrict__ ir, int t) {
    int p = blockIdx.x * 2 + threadIdx.y;
    int b = threadIdx.x;
    float l  = g_actT[il[g_pi[p]] * BSZ + b];
    float rr = g_actT[ir[g_pj[p]] * BSZ + b];
    float r = g_r[p];
    float a = r * g_alpha[p * BSZ + b] + l * rr;
    g_alpha[p * BSZ + b] = a;
    float beta = 1.0f;
    for (int k = 0; k <= t; k++) beta = r * beta + 1.0f;
    float s = a / sqrtf(beta);
    tf_store(s, p, b, g_syncF);
}

// ---------------- wide split-K reduce + bias + preds ----------------
__global__ __launch_bounds__(256) void k_reduce(const float* __restrict__ outb,
                                                float* __restrict__ dout, int t) {
    int idx = blockIdx.x * 256 + threadIdx.x;
    if (idx >= BSZ * OUTD) return;
    int b = idx / OUTD, n = idx - b * OUTD;
    float v = outb[n];
#pragma unroll
    for (int s = 0; s < SK2; s++) v += g_part[(s * BSZ + b) * OUTD + n];
    g_pred[idx] = v;
    dout[(b * OUTD + n) * NITER + t] = v;
}

// ---------------- entropy / certainty ----------------
__global__ __launch_bounds__(256) void k_finish(float* __restrict__ dout, int t) {
    int b = blockIdx.x, tid = threadIdx.x;
    __shared__ float red[256];
    const float* sp = g_pred + b * OUTD;
    float mx = -3.4e38f;
    for (int n = tid; n < OUTD; n += 256) mx = fmaxf(mx, sp[n]);
    red[tid] = mx; __syncthreads();
    for (int s = 128; s > 0; s >>= 1) { if (tid < s) red[tid] = fmaxf(red[tid], red[tid + s]); __syncthreads(); }
    float smax = red[0];
    __syncthreads();
    float se = 0.f;
    for (int n = tid; n < OUTD; n += 256) se += expf(sp[n] - smax);
    red[tid] = se; __syncthreads();
    for (int s = 128; s > 0; s >>= 1) { if (tid < s) red[tid] += red[tid + s]; __syncthreads(); }
    float lse = smax + logf(red[0]);
    __syncthreads();
    float ent = 0.f;
    for (int n = tid; n < OUTD; n += 256) { float lp = sp[n] - lse; ent += expf(lp) * lp; }
    red[tid] = ent; __syncthreads();
    for (int s = 128; s > 0; s >>= 1) { if (tid < s) red[tid] += red[tid + s]; __syncthreads(); }
    if (tid == 0) {
        float ne = -red[0] / logf(1000.0f);
        dout[CERT_OFF + (b * 2 + 0) * NITER + t] = ne;
        dout[CERT_OFF + (b * 2 + 1) * NITER + t] = 1.0f - ne;
    }
}

// ---------------- host ----------------
extern "C" void kernel_launch(void* const* d_in, const int* in_sizes, int n_in,
                              void* d_out, int out_size) {
    const float* x      = (const float*)d_in[0];
    const float* syn_w  = (const float*)d_in[1];
    const float* syn_b  = (const float*)d_in[2];
    const float* ln_g   = (const float*)d_in[3];
    const float* ln_b   = (const float*)d_in[4];
    const float* tp_w1  = (const float*)d_in[5];
    const float* tp_b1  = (const float*)d_in[6];
    const float* tp_w2  = (const float*)d_in[7];
    const float* tp_b2  = (const float*)d_in[8];
    const float* sas    = (const float*)d_in[9];
    const float* strc   = (const float*)d_in[10];
    const float* decay  = (const float*)d_in[11];
    const float* out_w  = (const float*)d_in[12];
    const float* out_b  = (const float*)d_in[13];
    const int*   il     = (const int*)d_in[14];
    const int*   ir     = (const int*)d_in[15];
    float* out = (float*)d_out;

    float *p_xT, *p_z0, *p_zp, *p_part, *p_synB, *p_outB;
    U32 *p_actF, *p_syncF;
    cudaGetSymbolAddress((void**)&p_xT,    g_xT);
    cudaGetSymbolAddress((void**)&p_z0,    g_z0);
    cudaGetSymbolAddress((void**)&p_zp,    g_zp);
    cudaGetSymbolAddress((void**)&p_part,  g_part);
    cudaGetSymbolAddress((void**)&p_actF,  g_actF);
    cudaGetSymbolAddress((void**)&p_syncF, g_syncF);
    cudaGetSymbolAddress((void**)&p_synB,  g_synB);
    cudaGetSymbolAddress((void**)&p_outB,  g_outB);

    cudaFuncSetAttribute(k_gemm_mma, cudaFuncAttributeMaxDynamicSharedMemorySize, GSMEM);

    // side stream + events for overlapping the reduction tail with the next
    // iteration's front half (capture-legal fork/join; no device allocations)
    cudaStream_t sb;
    cudaStreamCreateWithFlags(&sb, cudaStreamNonBlocking);
    cudaEvent_t evG2[NITER], evRed[NITER], evFin;
    for (int t = 0; t < NITER; t++) {
        cudaEventCreateWithFlags(&evG2[t], cudaEventDisableTiming);
        cudaEventCreateWithFlags(&evRed[t], cudaEventDisableTiming);
    }
    cudaEventCreateWithFlags(&evFin, cudaEventDisableTiming);

    k_init_all<<<RTOT / 256, 256>>>(x, strc, sas, tp_w1, tp_w2);
    k_transpose_blk<<<dim3(N1 / 128, NKS1), 256>>>(syn_w + (size_t)DIN * N1, N1, NKS1, p_synB);
    k_transpose_blk<<<dim3(OUTPAD / 128, NKS2), 256>>>(out_w, OUTD, NKS2, p_outB);

    for (int t = 0; t < NITER; t++) {
        k_gemm_mma<<<dim3(N1 / 128, SK1), 256, GSMEM>>>(p_actF, p_synB,
                                                        NKS1, N1, SK1, p_zp, N1);
        if (t == 0) {
            k_gemm_f2<<<N1 / 128, 256>>>(p_xT, syn_w, N1, DIN / 8, p_z0, N1);
            k_init_alpha<<<NSYNC, BSZ>>>(sas, decay, il, ir);
        }
        k_glu_ln<<<BSZ, 256>>>(syn_b, ln_g, ln_b, t % MEMN);
        k_traceproc<<<DMODEL, BSZ>>>(tp_b1, tp_b2, t);
        k_syncpair<<<NSYNC / 2, dim3(BSZ, 2)>>>(il, ir, t);
        if (t > 0) cudaStreamWaitEvent(0, evRed[t - 1], 0);   // g_part reuse hazard
        k_gemm_mma<<<dim3(OUTPAD / 128, SK2), 256, GSMEM>>>(p_syncF, p_outB,
                                                            NKS2, OUTD, SK2, p_part, OUTD);
        cudaEventRecord(evG2[t], 0);
        cudaStreamWaitEvent(sb, evG2[t], 0);
        k_reduce<<<(BSZ * OUTD + 255) / 256, 256, 0, sb>>>(out_b, out, t);
        cudaEventRecord(evRed[t], sb);
        k_finish<<<BSZ, 256, 0, sb>>>(out, t);
    }
    // rejoin: origin stream must own the capture leaf
    cudaEventRecord(evFin, sb);
    cudaStreamWaitEvent(0, evFin, 0);
}